// round 3
// baseline (speedup 1.0000x reference)
#include <cuda_runtime.h>
#include <cuda_bf16.h>
#include <cstdint>

// Problem constants
#define TT   256     // sequence length
#define BB   32      // batch
#define EMB  256
#define HHD  256     // per-direction hidden
#define G4   1024    // 4*HHD
#define NT   12
#define START_IDX 10
#define STOP_IDX  11

typedef unsigned long long ull;

// ---------------- scratch (device globals; no allocation allowed) ----------
__device__ float g_zpre[2L * TT * G4 * BB];        // [dir][t][gate_row][b]  64 MB
__device__ float g_hs[2][(TT + 1) * HHD * BB];     // [dir][slot][k][b]     2x8.4 MB (transposed h)
__device__ float g_feats[BB * TT * NT];            // [b][t][tag]
__device__ int   g_bar[2 * TT];                    // per-dir per-step barrier counters

// ---------------- f32x2 helpers --------------------------------------------
__device__ __forceinline__ void fma2(ull& d, ull a, ull b) {
    asm volatile("fma.rn.f32x2 %0, %1, %2, %0;" : "+l"(d) : "l"(a), "l"(b));
}
__device__ __forceinline__ ull pack2(float x, float y) {
    ull r; asm("mov.b64 %0, {%1, %2};" : "=l"(r) : "f"(x), "f"(y)); return r;
}
__device__ __forceinline__ float2 unpack2(ull v) {
    float2 f; asm("mov.b64 {%0, %1}, %2;" : "=f"(f.x), "=f"(f.y) : "l"(v)); return f;
}
__device__ __forceinline__ int ldacq(const int* p) {
    int v; asm volatile("ld.acquire.gpu.global.s32 %0, [%1];" : "=r"(v) : "l"(p)); return v;
}
__device__ __forceinline__ void redrel(int* p) {
    asm volatile("red.release.gpu.global.add.s32 [%0], 1;" :: "l"(p));
}
__device__ __forceinline__ float sigf(float x) { return 1.0f / (1.0f + __expf(-x)); }

// ============================================================================
// K1: input GEMM.  z_pre[dir][t][g][b] = b[dir][g] + sum_e embed[sent[b][t]][e] * W_ih[dir][g][e]
// C[M=2048][N=8192], K=256.  BM=BN=128, BK=16, 256 thr, 8x8 tile via f32x2.
// ============================================================================
__global__ void __launch_bounds__(256) k_ingemm(
    const int* __restrict__ sent, const float* __restrict__ embed,
    const float* __restrict__ Wf, const float* __restrict__ Wb,
    const float* __restrict__ bf, const float* __restrict__ bb)
{
    __shared__ __align__(16) float As[16][128];   // [k][m]
    __shared__ __align__(16) float Bs[16][128];   // [k][n]
    __shared__ int idxs[128];

    const int tid = threadIdx.x;
    const int m0 = blockIdx.y * 128;   // gate-row dim (2048)
    const int n0 = blockIdx.x * 128;   // (t,b) dim (8192)

    if (tid < 128) {
        int n = n0 + tid;
        int t = n >> 5, b = n & 31;
        idxs[tid] = sent[b * TT + t];
    }
    __syncthreads();

    ull acc[8][4];
#pragma unroll
    for (int i = 0; i < 8; i++)
#pragma unroll
        for (int j = 0; j < 4; j++) acc[i][j] = 0ULL;

    const int tm0 = (tid >> 4) << 3;
    const int tn0 = (tid & 15) << 3;

    for (int k0 = 0; k0 < 256; k0 += 16) {
#pragma unroll
        for (int i = 0; i < 2; i++) {
            int s = tid + i * 256;          // 0..511
            int row = s >> 2;               // 0..127
            int kq = (s & 3) << 2;          // 0,4,8,12
            // A tile
            int gm = m0 + row;
            const float* W = (gm < 1024) ? Wf : Wb;
            int g = gm & 1023;
            float4 v = *(const float4*)(W + g * 256 + k0 + kq);
            As[kq + 0][row] = v.x; As[kq + 1][row] = v.y;
            As[kq + 2][row] = v.z; As[kq + 3][row] = v.w;
            // B tile (embedding gather)
            long e = (long)idxs[row] * 256 + k0 + kq;
            float4 u = *(const float4*)(embed + e);
            Bs[kq + 0][row] = u.x; Bs[kq + 1][row] = u.y;
            Bs[kq + 2][row] = u.z; Bs[kq + 3][row] = u.w;
        }
        __syncthreads();
#pragma unroll
        for (int k = 0; k < 16; k++) {
            float4 a0 = *(const float4*)&As[k][tm0];
            float4 a1 = *(const float4*)&As[k][tm0 + 4];
            const ull* brow = (const ull*)&Bs[k][tn0];
            ull b0 = brow[0], b1 = brow[1], b2 = brow[2], b3 = brow[3];
            float av[8] = {a0.x, a0.y, a0.z, a0.w, a1.x, a1.y, a1.z, a1.w};
#pragma unroll
            for (int i = 0; i < 8; i++) {
                ull a2 = pack2(av[i], av[i]);
                fma2(acc[i][0], a2, b0);
                fma2(acc[i][1], a2, b1);
                fma2(acc[i][2], a2, b2);
                fma2(acc[i][3], a2, b3);
            }
        }
        __syncthreads();
    }

    // epilogue: bias + scattered store into z_pre[dir][t][g][b]
#pragma unroll
    for (int i = 0; i < 8; i++) {
        int gm = m0 + tm0 + i;
        int dir = gm >> 10;
        int g = gm & 1023;
        float bias = dir ? bb[g] : bf[g];
#pragma unroll
        for (int j = 0; j < 4; j++) {
            float2 v = unpack2(acc[i][j]);
            int n = n0 + tn0 + j * 2;
            int t = n >> 5, b = n & 31;
            long off = ((long)dir * TT + t) * (G4 * BB) + (long)g * BB + b;
            g_zpre[off]     = v.x + bias;
            g_zpre[off + 1] = v.y + bias;
        }
    }
}

// ============================================================================
// K1b: initialize h slots (transposed) and zero barriers
// ============================================================================
__global__ void k_inith(const float* __restrict__ h0)
{
    int dir = blockIdx.x;
    int tid = threadIdx.x;   // 256
    long slot = (dir == 0) ? 0 : TT;
    for (int s = tid; s < HHD * BB; s += 256) {
        int k = s >> 5, b = s & 31;
        g_hs[dir][slot * (HHD * BB) + s] = h0[dir * (BB * HHD) + b * HHD + k];
    }
    if (blockIdx.x == 0) {
        for (int i = tid; i < 2 * TT; i += 256) g_bar[i] = 0;
    }
}

// ============================================================================
// K2: persistent bi-directional LSTM recurrence.
// 128 CTAs: dir = cid>>6, j-group = cid&63 (4 hidden units each).
// W_hh slice (16 rows x 256) resident in SMEM for all 256 steps.
// lane = batch, warp = 32-wide k chunk; W reads are SMEM broadcasts.
// Per-direction global spin barrier per step (64 CTAs, all co-resident).
// ============================================================================
__global__ void __launch_bounds__(256, 1) k_lstm(
    const float* __restrict__ Whf, const float* __restrict__ Whb,
    const float* __restrict__ c0)
{
    __shared__ __align__(16) float Wsm[16][256];
    __shared__ float zred[8][16][32];
    __shared__ float zfin[16][32];
    __shared__ float csm[4][32];

    const int tid = threadIdx.x;
    const int w = tid >> 5, l = tid & 31;
    const int cid = blockIdx.x;
    const int dir = cid >> 6;
    const int j0 = (cid & 63) * 4;

    const float* Wh = dir ? Whb : Whf;
    // load W slice: rows r = gate*4 + jj  -> W_hh[gate*256 + j0+jj][k]
#pragma unroll
    for (int i = 0; i < 4; i++) {
        int s = tid + i * 256;          // 0..1023 float4 slots
        int r = s >> 6;                 // 0..15
        int kq = (s & 63) << 2;
        int gate = r >> 2, jj = r & 3;
        float4 v = *(const float4*)(Wh + (gate * HHD + j0 + jj) * HHD + kq);
        *(float4*)&Wsm[r][kq] = v;
    }
    if (tid < 128) {
        int jj = tid >> 5, b = tid & 31;
        csm[jj][b] = c0[dir * (BB * HHD) + b * HHD + j0 + jj];
    }
    __syncthreads();

    float* hsBase = g_hs[dir];
    int* bar = g_bar + dir * TT;

    for (int s = 0; s < TT; s++) {
        if (s > 0) {
            if (tid == 0) {
                while (ldacq(&bar[s - 1]) < 64) __nanosleep(32);
            }
            __syncthreads();
        }
        const int t = (dir == 0) ? s : (TT - 1 - s);
        const int rslot = (dir == 0) ? s : (t + 1);
        const int wslot = (dir == 0) ? (s + 1) : t;
        const float* hp = hsBase + (long)rslot * (HHD * BB);

        // load this warp's k-chunk of h (transposed layout -> coalesced), packed
        ull hreg2[16];
#pragma unroll
        for (int q = 0; q < 16; q++) {
            float x0 = hp[(w * 32 + 2 * q) * BB + l];
            float x1 = hp[(w * 32 + 2 * q + 1) * BB + l];
            hreg2[q] = pack2(x0, x1);
        }
        // partial dot products: 16 rows, k-chunk of 32
#pragma unroll
        for (int r = 0; r < 16; r++) {
            const ull* W2 = (const ull*)&Wsm[r][w * 32];
            ull a0 = 0ULL, a1 = 0ULL;
#pragma unroll
            for (int q = 0; q < 16; q += 2) {
                fma2(a0, W2[q],     hreg2[q]);
                fma2(a1, W2[q + 1], hreg2[q + 1]);
            }
            float2 f0 = unpack2(a0), f1 = unpack2(a1);
            zred[w][r][l] = (f0.x + f0.y) + (f1.x + f1.y);
        }
        __syncthreads();

        // reduce 8 warp-partials + add z_pre
#pragma unroll
        for (int i = 0; i < 2; i++) {
            int idx = tid + i * 256;
            int r = idx >> 5, b = idx & 31;
            float z = 0.f;
#pragma unroll
            for (int ww = 0; ww < 8; ww++) z += zred[ww][r][b];
            int gate = r >> 2, jj = r & 3;
            long off = ((long)dir * TT + t) * (G4 * BB) + (long)(gate * HHD + j0 + jj) * BB + b;
            zfin[r][b] = z + g_zpre[off];
        }
        __syncthreads();

        // gates -> c,h ; write h (transposed) to its slot
        if (tid < 128) {
            int jj = tid >> 5, b = tid & 31;
            float zi = zfin[0 * 4 + jj][b];
            float zf = zfin[1 * 4 + jj][b];
            float zg = zfin[2 * 4 + jj][b];
            float zo = zfin[3 * 4 + jj][b];
            float c = sigf(zf) * csm[jj][b] + sigf(zi) * tanhf(zg);
            csm[jj][b] = c;
            float h = sigf(zo) * tanhf(c);
            hsBase[(long)wslot * (HHD * BB) + (j0 + jj) * BB + b] = h;
        }
        __threadfence();
        __syncthreads();
        if (tid == 0) redrel(&bar[s]);
    }
}

// ============================================================================
// K3: output projection. feats[b][t][tag] = b_out[tag] + sum_k h_cat[k]*W_out[tag][k]
// ============================================================================
__global__ void __launch_bounds__(128) k_proj(
    const float* __restrict__ Wout, const float* __restrict__ bout)
{
    extern __shared__ float sm[];     // [2][256][32] = 64 KB
    const int t = blockIdx.x;
    const int tid = threadIdx.x;

    const float4* hf = (const float4*)(g_hs[0] + (long)(t + 1) * (HHD * BB));
    const float4* hb = (const float4*)(g_hs[1] + (long)t * (HHD * BB));
    float4* smf = (float4*)sm;
    float4* smb = (float4*)(sm + HHD * BB);
    for (int i = tid; i < (HHD * BB) / 4; i += 128) {
        smf[i] = hf[i];
        smb[i] = hb[i];
    }
    __syncthreads();

    const float* sf = sm;
    const float* sb = sm + HHD * BB;
    for (int o = tid; o < BB * NT; o += 128) {
        int b = o / NT, tag = o % NT;
        float acc = bout[tag];
        const float* wr = Wout + tag * 512;
#pragma unroll 8
        for (int k = 0; k < 256; k++) acc += sf[k * BB + b] * wr[k];
#pragma unroll 8
        for (int k = 0; k < 256; k++) acc += sb[k * BB + b] * wr[256 + k];
        g_feats[(b * TT + t) * NT + tag] = acc;
    }
}

// ============================================================================
// K4: Viterbi decode (one warp per batch element) + backtrace.
// out[0..31] = scores ; out[32 + b*T + t] = path tag (as float)
// ============================================================================
__global__ void __launch_bounds__(32) k_viterbi(
    const float* __restrict__ trans, float* __restrict__ out)
{
    __shared__ float tsm[NT * NT];
    __shared__ float fv[NT];
    __shared__ signed char bp[TT][NT];

    const int b = blockIdx.x;
    const int tid = threadIdx.x;

    for (int i = tid; i < NT * NT; i += 32) tsm[i] = trans[i];
    if (tid < NT) fv[tid] = (tid == START_IDX) ? 0.0f : -10000.0f;
    __syncwarp();

    const float* fb = g_feats + (long)b * TT * NT;
    for (int t = 0; t < TT; t++) {
        float bestv = -1e30f; int bestp = 0;
        if (tid < NT) {
            bestv = fv[0] + tsm[tid * NT + 0]; bestp = 0;
#pragma unroll
            for (int p = 1; p < NT; p++) {
                float v = fv[p] + tsm[tid * NT + p];
                if (v > bestv) { bestv = v; bestp = p; }
            }
        }
        __syncwarp();
        if (tid < NT) {
            fv[tid] = bestv + fb[t * NT + tid];
            bp[t][tid] = (signed char)bestp;
        }
        __syncwarp();
    }

    if (tid == 0) {
        float best = fv[0] + tsm[STOP_IDX * NT + 0]; int bt = 0;
#pragma unroll
        for (int n = 1; n < NT; n++) {
            float v = fv[n] + tsm[STOP_IDX * NT + n];
            if (v > best) { best = v; bt = n; }
        }
        out[b] = best;
        int tag = bt;
        for (int t = TT - 1; t >= 0; t--) {
            out[32 + b * TT + t] = (float)tag;
            tag = bp[t][tag];
        }
    }
}

// ============================================================================
extern "C" void kernel_launch(void* const* d_in, const int* in_sizes, int n_in,
                              void* d_out, int out_size)
{
    const int*   sent  = (const int*)  d_in[0];
    const float* embed = (const float*)d_in[1];
    const float* Wihf  = (const float*)d_in[2];
    const float* Whhf  = (const float*)d_in[3];
    const float* bf    = (const float*)d_in[4];
    const float* Wihb  = (const float*)d_in[5];
    const float* Whhb  = (const float*)d_in[6];
    const float* bb    = (const float*)d_in[7];
    const float* Wout  = (const float*)d_in[8];
    const float* bout  = (const float*)d_in[9];
    const float* trans = (const float*)d_in[10];
    const float* h0    = (const float*)d_in[11];
    const float* c0    = (const float*)d_in[12];
    float* out = (float*)d_out;

    cudaFuncSetAttribute(k_proj, cudaFuncAttributeMaxDynamicSharedMemorySize, 65536);

    k_ingemm<<<dim3(64, 16), 256>>>(sent, embed, Wihf, Wihb, bf, bb);
    k_inith<<<2, 256>>>(h0);
    k_lstm<<<128, 256>>>(Whhf, Whhb, c0);
    k_proj<<<TT, 128, 65536>>>(Wout, bout);
    k_viterbi<<<BB, 32>>>(trans, out);
}

// round 4
// speedup vs baseline: 1.2187x; 1.2187x over previous
#include <cuda_runtime.h>
#include <cuda_bf16.h>
#include <cstdint>

// Problem constants
#define TT   256     // sequence length
#define BB   32      // batch
#define EMB  256
#define HHD  256     // per-direction hidden
#define G4   1024    // 4*HHD
#define NT   12
#define START_IDX 10
#define STOP_IDX  11

typedef unsigned long long ull;

// ---------------- scratch (device globals; no allocation allowed) ----------
__device__ float g_zpre[2L * TT * G4 * BB];        // [dir][t][gate_row][b]
// h stored PAIR-PACKED: linear idx = slot*8192 + (k>>1)*64 + b*2 + (k&1)
__device__ float g_hs[2][(TT + 1) * HHD * BB];
__device__ float g_feats[BB * TT * NT];            // [b][t][tag]
__device__ int   g_bar[2 * TT];                    // per-dir per-step barrier counters

// ---------------- helpers ---------------------------------------------------
__device__ __forceinline__ void fma2(ull& d, ull a, ull b) {
    asm volatile("fma.rn.f32x2 %0, %1, %2, %0;" : "+l"(d) : "l"(a), "l"(b));
}
__device__ __forceinline__ ull pack2(float x, float y) {
    ull r; asm("mov.b64 %0, {%1, %2};" : "=l"(r) : "f"(x), "f"(y)); return r;
}
__device__ __forceinline__ float2 unpack2(ull v) {
    float2 f; asm("mov.b64 {%0, %1}, %2;" : "=f"(f.x), "=f"(f.y) : "l"(v)); return f;
}
__device__ __forceinline__ int ldacq(const int* p) {
    int v; asm volatile("ld.acquire.gpu.global.s32 %0, [%1];" : "=r"(v) : "l"(p)); return v;
}
__device__ __forceinline__ void redrel(int* p) {
    asm volatile("red.release.gpu.global.add.s32 [%0], 1;" :: "l"(p));
}
__device__ __forceinline__ float sigf(float x) { return 1.0f / (1.0f + __expf(-x)); }

// ============================================================================
// K1: input GEMM.  z_pre[dir][t][g][b] = b[dir][g] + sum_e embed[sent[b][t]][e] * W_ih[dir][g][e]
// C[M=2048][N=8192], K=256.  BM=BN=128, BK=16, 256 thr, 8x8 tile via f32x2.
// ============================================================================
__global__ void __launch_bounds__(256) k_ingemm(
    const int* __restrict__ sent, const float* __restrict__ embed,
    const float* __restrict__ Wf, const float* __restrict__ Wb,
    const float* __restrict__ bf, const float* __restrict__ bb)
{
    __shared__ __align__(16) float As[16][128];   // [k][m]
    __shared__ __align__(16) float Bs[16][128];   // [k][n]
    __shared__ int idxs[128];

    const int tid = threadIdx.x;
    const int m0 = blockIdx.y * 128;   // gate-row dim (2048)
    const int n0 = blockIdx.x * 128;   // (t,b) dim (8192)

    if (tid < 128) {
        int n = n0 + tid;
        int t = n >> 5, b = n & 31;
        idxs[tid] = sent[b * TT + t];
    }
    __syncthreads();

    ull acc[8][4];
#pragma unroll
    for (int i = 0; i < 8; i++)
#pragma unroll
        for (int j = 0; j < 4; j++) acc[i][j] = 0ULL;

    const int tm0 = (tid >> 4) << 3;
    const int tn0 = (tid & 15) << 3;

    for (int k0 = 0; k0 < 256; k0 += 16) {
#pragma unroll
        for (int i = 0; i < 2; i++) {
            int s = tid + i * 256;          // 0..511
            int row = s >> 2;               // 0..127
            int kq = (s & 3) << 2;          // 0,4,8,12
            int gm = m0 + row;
            const float* W = (gm < 1024) ? Wf : Wb;
            int g = gm & 1023;
            float4 v = *(const float4*)(W + g * 256 + k0 + kq);
            As[kq + 0][row] = v.x; As[kq + 1][row] = v.y;
            As[kq + 2][row] = v.z; As[kq + 3][row] = v.w;
            long e = (long)idxs[row] * 256 + k0 + kq;
            float4 u = *(const float4*)(embed + e);
            Bs[kq + 0][row] = u.x; Bs[kq + 1][row] = u.y;
            Bs[kq + 2][row] = u.z; Bs[kq + 3][row] = u.w;
        }
        __syncthreads();
#pragma unroll
        for (int k = 0; k < 16; k++) {
            float4 a0 = *(const float4*)&As[k][tm0];
            float4 a1 = *(const float4*)&As[k][tm0 + 4];
            const ull* brow = (const ull*)&Bs[k][tn0];
            ull b0 = brow[0], b1 = brow[1], b2 = brow[2], b3 = brow[3];
            float av[8] = {a0.x, a0.y, a0.z, a0.w, a1.x, a1.y, a1.z, a1.w};
#pragma unroll
            for (int i = 0; i < 8; i++) {
                ull a2 = pack2(av[i], av[i]);
                fma2(acc[i][0], a2, b0);
                fma2(acc[i][1], a2, b1);
                fma2(acc[i][2], a2, b2);
                fma2(acc[i][3], a2, b3);
            }
        }
        __syncthreads();
    }

#pragma unroll
    for (int i = 0; i < 8; i++) {
        int gm = m0 + tm0 + i;
        int dir = gm >> 10;
        int g = gm & 1023;
        float bias = dir ? bb[g] : bf[g];
#pragma unroll
        for (int j = 0; j < 4; j++) {
            float2 v = unpack2(acc[i][j]);
            int n = n0 + tn0 + j * 2;
            int t = n >> 5, b = n & 31;
            long off = ((long)dir * TT + t) * (G4 * BB) + (long)g * BB + b;
            g_zpre[off]     = v.x + bias;
            g_zpre[off + 1] = v.y + bias;
        }
    }
}

// ============================================================================
// K1b: initialize h slots (pair-packed) and zero barriers
// ============================================================================
__global__ void k_inith(const float* __restrict__ h0)
{
    int dir = blockIdx.x;
    int tid = threadIdx.x;   // 256
    int slot = (dir == 0) ? 0 : TT;
    for (int s = tid; s < HHD * BB; s += 256) {
        int k = s >> 5, b = s & 31;
        int idx = slot * (HHD * BB) + (k >> 1) * 64 + b * 2 + (k & 1);
        g_hs[dir][idx] = h0[dir * (BB * HHD) + b * HHD + k];
    }
    if (blockIdx.x == 0) {
        for (int i = tid; i < 2 * TT; i += 256) g_bar[i] = 0;
    }
}

// ============================================================================
// K2: persistent bi-directional LSTM recurrence.
// 128 CTAs: dir = cid>>6, j-group = cid&63 (4 hidden units each).
// W_hh slice (16 rows x 256) resident in SMEM for all 256 steps.
// lane = batch, warp = 32-wide k chunk; W reads are SMEM broadcasts.
// z_pre prefetched into registers BEFORE the step barrier (latency hidden).
// release/acquire barrier (no threadfence); fused reduce+gate phase.
// ============================================================================
__global__ void __launch_bounds__(256, 1) k_lstm(
    const float* __restrict__ Whf, const float* __restrict__ Whb,
    const float* __restrict__ c0)
{
    __shared__ __align__(16) float Wsm[16][256];
    __shared__ float zred[8][16][32];
    __shared__ float csm[4][32];

    const int tid = threadIdx.x;
    const int w = tid >> 5, l = tid & 31;
    const int cid = blockIdx.x;
    const int dir = cid >> 6;
    const int j0 = (cid & 63) * 4;
    const int jj = (tid >> 5) & 3;   // for tid<128: warp index = jj
    const int b  = l;

    const float* Wh = dir ? Whb : Whf;
#pragma unroll
    for (int i = 0; i < 4; i++) {
        int s = tid + i * 256;          // 0..1023 float4 slots
        int r = s >> 6;                 // 0..15
        int kq = (s & 63) << 2;
        int gate = r >> 2, jr = r & 3;
        float4 v = *(const float4*)(Wh + (gate * HHD + j0 + jr) * HHD + kq);
        *(float4*)&Wsm[r][kq] = v;
    }
    if (tid < 128) {
        csm[jj][b] = c0[dir * (BB * HHD) + b * HHD + j0 + jj];
    }
    __syncthreads();

    float* hsBase = g_hs[dir];
    int* bar = g_bar + dir * TT;
    const int zdirbase = dir * (TT * G4 * BB);

    for (int s = 0; s < TT; s++) {
        const int t = (dir == 0) ? s : (TT - 1 - s);
        const int rslot = (dir == 0) ? s : (t + 1);
        const int wslot = (dir == 0) ? (s + 1) : t;

        // ---- prefetch z_pre for this step (independent of barrier) ----
        float zp0, zp1, zp2, zp3;
        if (tid < 128) {
            const float* zb = g_zpre + zdirbase + t * (G4 * BB) + (j0 + jj) * BB + b;
            zp0 = zb[0 * HHD * BB];
            zp1 = zb[1 * HHD * BB];
            zp2 = zb[2 * HHD * BB];
            zp3 = zb[3 * HHD * BB];
        }

        // ---- wait for previous step's h ----
        if (s > 0) {
            if (tid == 0) {
                while (ldacq(&bar[s - 1]) < 64) { }
            }
            __syncthreads();
        }

        // ---- load this warp's k-chunk of h (pair-packed -> LDG.64) ----
        const ull* hp2 = (const ull*)(hsBase + rslot * (HHD * BB)) + (w * 16) * 32 + l;
        ull hreg2[16];
#pragma unroll
        for (int q = 0; q < 16; q++) hreg2[q] = hp2[q * 32];

        // ---- partial dot products: 16 rows, k-chunk of 32 ----
#pragma unroll
        for (int r = 0; r < 16; r++) {
            const ull* W2 = (const ull*)&Wsm[r][w * 32];
            ull a0 = 0ULL, a1 = 0ULL;
#pragma unroll
            for (int q = 0; q < 16; q += 2) {
                fma2(a0, W2[q],     hreg2[q]);
                fma2(a1, W2[q + 1], hreg2[q + 1]);
            }
            float2 f0 = unpack2(a0), f1 = unpack2(a1);
            zred[w][r][l] = (f0.x + f0.y) + (f1.x + f1.y);
        }
        __syncthreads();

        // ---- fused reduce + gates + h write (threads 0..127) ----
        if (tid < 128) {
            float zi = zp0, zf = zp1, zg = zp2, zo = zp3;
#pragma unroll
            for (int ww = 0; ww < 8; ww++) {
                zi += zred[ww][0 * 4 + jj][b];
                zf += zred[ww][1 * 4 + jj][b];
                zg += zred[ww][2 * 4 + jj][b];
                zo += zred[ww][3 * 4 + jj][b];
            }
            float c = sigf(zf) * csm[jj][b] + sigf(zi) * tanhf(zg);
            csm[jj][b] = c;
            float h = sigf(zo) * tanhf(c);
            int j = j0 + jj;
            hsBase[wslot * (HHD * BB) + (j >> 1) * 64 + b * 2 + (j & 1)] = h;
        }
        __syncthreads();
        if (tid == 0) redrel(&bar[s]);   // release orders the STG h above
    }
}

// ============================================================================
// K3: output projection. warp = tag (12 warps), lane = b.
// feats[b][t][tag] = b_out[tag] + sum_k h_cat[k][b]*W_out[tag][k]
// ============================================================================
__global__ void __launch_bounds__(384) k_proj(
    const float* __restrict__ Wout, const float* __restrict__ bout)
{
    __shared__ float Ws[NT * 512];    // 24 KB
    const int t = blockIdx.x;
    const int tid = threadIdx.x;
    const int tag = tid >> 5;         // 0..11
    const int l = tid & 31;           // batch

    for (int i = tid; i < NT * 512; i += 384) Ws[i] = Wout[i];
    __syncthreads();

    const float* hf = g_hs[0] + (t + 1) * (HHD * BB);   // pair-packed
    const float* hb = g_hs[1] + t * (HHD * BB);
    const float* wr = Ws + tag * 512;

    float a0 = 0.f, a1 = 0.f, a2 = 0.f, a3 = 0.f;
#pragma unroll 8
    for (int k = 0; k < 256; k += 4) {
        float2 v0 = *(const float2*)(hf + (k >> 1) * 64 + l * 2);
        float2 v1 = *(const float2*)(hf + ((k >> 1) + 1) * 64 + l * 2);
        a0 += wr[k]     * v0.x;
        a1 += wr[k + 1] * v0.y;
        a2 += wr[k + 2] * v1.x;
        a3 += wr[k + 3] * v1.y;
    }
#pragma unroll 8
    for (int k = 0; k < 256; k += 4) {
        float2 v0 = *(const float2*)(hb + (k >> 1) * 64 + l * 2);
        float2 v1 = *(const float2*)(hb + ((k >> 1) + 1) * 64 + l * 2);
        a0 += wr[256 + k]     * v0.x;
        a1 += wr[256 + k + 1] * v0.y;
        a2 += wr[256 + k + 2] * v1.x;
        a3 += wr[256 + k + 3] * v1.y;
    }
    float acc = ((a0 + a1) + (a2 + a3)) + bout[tag];
    g_feats[(l * TT + t) * NT + tag] = acc;
}

// ============================================================================
// K4: Viterbi decode (one warp per batch element) + backtrace.
// out[0..31] = scores ; out[32 + b*T + t] = path tag (as float)
// ============================================================================
__global__ void __launch_bounds__(32) k_viterbi(
    const float* __restrict__ trans, float* __restrict__ out)
{
    __shared__ float tsm[NT * NT];
    __shared__ float fv[NT];
    __shared__ signed char bp[TT][NT];

    const int b = blockIdx.x;
    const int tid = threadIdx.x;

    for (int i = tid; i < NT * NT; i += 32) tsm[i] = trans[i];
    if (tid < NT) fv[tid] = (tid == START_IDX) ? 0.0f : -10000.0f;
    __syncwarp();

    const float* fb = g_feats + (long)b * TT * NT;
    for (int t = 0; t < TT; t++) {
        float bestv = -1e30f; int bestp = 0;
        if (tid < NT) {
            bestv = fv[0] + tsm[tid * NT + 0]; bestp = 0;
#pragma unroll
            for (int p = 1; p < NT; p++) {
                float v = fv[p] + tsm[tid * NT + p];
                if (v > bestv) { bestv = v; bestp = p; }
            }
        }
        __syncwarp();
        if (tid < NT) {
            fv[tid] = bestv + fb[t * NT + tid];
            bp[t][tid] = (signed char)bestp;
        }
        __syncwarp();
    }

    if (tid == 0) {
        float best = fv[0] + tsm[STOP_IDX * NT + 0]; int bt = 0;
#pragma unroll
        for (int n = 1; n < NT; n++) {
            float v = fv[n] + tsm[STOP_IDX * NT + n];
            if (v > best) { best = v; bt = n; }
        }
        out[b] = best;
        int tag = bt;
        for (int t = TT - 1; t >= 0; t--) {
            out[32 + b * TT + t] = (float)tag;
            tag = bp[t][tag];
        }
    }
}

// ============================================================================
extern "C" void kernel_launch(void* const* d_in, const int* in_sizes, int n_in,
                              void* d_out, int out_size)
{
    const int*   sent  = (const int*)  d_in[0];
    const float* embed = (const float*)d_in[1];
    const float* Wihf  = (const float*)d_in[2];
    const float* Whhf  = (const float*)d_in[3];
    const float* bf    = (const float*)d_in[4];
    const float* Wihb  = (const float*)d_in[5];
    const float* Whhb  = (const float*)d_in[6];
    const float* bb    = (const float*)d_in[7];
    const float* Wout  = (const float*)d_in[8];
    const float* bout  = (const float*)d_in[9];
    const float* trans = (const float*)d_in[10];
    const float* h0    = (const float*)d_in[11];
    const float* c0    = (const float*)d_in[12];
    float* out = (float*)d_out;

    k_ingemm<<<dim3(64, 16), 256>>>(sent, embed, Wihf, Wihb, bf, bb);
    k_inith<<<2, 256>>>(h0);
    k_lstm<<<128, 256>>>(Whhf, Whhb, c0);
    k_proj<<<TT, 384>>>(Wout, bout);
    k_viterbi<<<BB, 32>>>(trans, out);
}

// round 5
// speedup vs baseline: 1.2245x; 1.0048x over previous
#include <cuda_runtime.h>
#include <cuda_bf16.h>
#include <cstdint>

// Problem constants
#define TT   256     // sequence length
#define BB   32      // batch
#define EMB  256
#define HHD  256     // per-direction hidden
#define G4   1024    // 4*HHD
#define NT   12
#define START_IDX 10
#define STOP_IDX  11

typedef unsigned long long ull;

// ---------------- scratch (device globals; no allocation allowed) ----------
__device__ __align__(16) float g_zpre[2L * TT * G4 * BB];   // [dir][t][gate_row][b]
// h stored PAIR-PACKED: linear idx = slot*8192 + (k>>1)*64 + b*2 + (k&1)
__device__ __align__(16) float g_hs[2][(TT + 1) * HHD * BB];
__device__ __align__(16) float g_feats[BB * TT * NT];       // [b][t][tag]
__device__ int   g_bar[2 * TT];                             // per-dir per-step counters

// ---------------- helpers ---------------------------------------------------
__device__ __forceinline__ void fma2(ull& d, ull a, ull b) {
    asm volatile("fma.rn.f32x2 %0, %1, %2, %0;" : "+l"(d) : "l"(a), "l"(b));
}
__device__ __forceinline__ ull pack2(float x, float y) {
    ull r; asm("mov.b64 %0, {%1, %2};" : "=l"(r) : "f"(x), "f"(y)); return r;
}
__device__ __forceinline__ float2 unpack2(ull v) {
    float2 f; asm("mov.b64 {%0, %1}, %2;" : "=f"(f.x), "=f"(f.y) : "l"(v)); return f;
}
__device__ __forceinline__ int ldacq(const int* p) {
    int v; asm volatile("ld.acquire.gpu.global.s32 %0, [%1];" : "=r"(v) : "l"(p)); return v;
}
__device__ __forceinline__ void redrel(int* p) {
    asm volatile("red.release.gpu.global.add.s32 [%0], 1;" :: "l"(p));
}
__device__ __forceinline__ float sigf(float x) { return 1.0f / (1.0f + __expf(-x)); }

// ============================================================================
// K1: input GEMM.  z_pre[dir][t][g][b] = b[dir][g] + sum_e embed[sent[b][t]][e] * W_ih[dir][g][e]
// C[M=2048][N=8192], K=256.  BM=BN=128, BK=16, 256 thr, 8x8 tile via f32x2.
// fma2-issue-bound (~130us floor on fp32); LDS/MOV overhead fits spare slots.
// ============================================================================
__global__ void __launch_bounds__(256) k_ingemm(
    const int* __restrict__ sent, const float* __restrict__ embed,
    const float* __restrict__ Wf, const float* __restrict__ Wb,
    const float* __restrict__ bf, const float* __restrict__ bb)
{
    __shared__ __align__(16) float As[16][128];   // [k][m]
    __shared__ __align__(16) float Bs[16][128];   // [k][n]
    __shared__ int idxs[128];

    const int tid = threadIdx.x;
    const int m0 = blockIdx.y * 128;   // gate-row dim (2048)
    const int n0 = blockIdx.x * 128;   // (t,b) dim (8192)

    if (tid < 128) {
        int n = n0 + tid;
        int t = n >> 5, b = n & 31;
        idxs[tid] = sent[b * TT + t];
    }
    __syncthreads();

    ull acc[8][4];
#pragma unroll
    for (int i = 0; i < 8; i++)
#pragma unroll
        for (int j = 0; j < 4; j++) acc[i][j] = 0ULL;

    const int tm0 = (tid >> 4) << 3;
    const int tn0 = (tid & 15) << 3;

    for (int k0 = 0; k0 < 256; k0 += 16) {
#pragma unroll
        for (int i = 0; i < 2; i++) {
            int s = tid + i * 256;          // 0..511
            int row = s >> 2;               // 0..127
            int kq = (s & 3) << 2;          // 0,4,8,12
            int gm = m0 + row;
            const float* W = (gm < 1024) ? Wf : Wb;
            int g = gm & 1023;
            float4 v = *(const float4*)(W + g * 256 + k0 + kq);
            As[kq + 0][row] = v.x; As[kq + 1][row] = v.y;
            As[kq + 2][row] = v.z; As[kq + 3][row] = v.w;
            long e = (long)idxs[row] * 256 + k0 + kq;
            float4 u = *(const float4*)(embed + e);
            Bs[kq + 0][row] = u.x; Bs[kq + 1][row] = u.y;
            Bs[kq + 2][row] = u.z; Bs[kq + 3][row] = u.w;
        }
        __syncthreads();
#pragma unroll
        for (int k = 0; k < 16; k++) {
            float4 a0 = *(const float4*)&As[k][tm0];
            float4 a1 = *(const float4*)&As[k][tm0 + 4];
            const ull* brow = (const ull*)&Bs[k][tn0];
            ull b0 = brow[0], b1 = brow[1], b2 = brow[2], b3 = brow[3];
            float av[8] = {a0.x, a0.y, a0.z, a0.w, a1.x, a1.y, a1.z, a1.w};
#pragma unroll
            for (int i = 0; i < 8; i++) {
                ull a2 = pack2(av[i], av[i]);
                fma2(acc[i][0], a2, b0);
                fma2(acc[i][1], a2, b1);
                fma2(acc[i][2], a2, b2);
                fma2(acc[i][3], a2, b3);
            }
        }
        __syncthreads();
    }

#pragma unroll
    for (int i = 0; i < 8; i++) {
        int gm = m0 + tm0 + i;
        int dir = gm >> 10;
        int g = gm & 1023;
        float bias = dir ? bb[g] : bf[g];
#pragma unroll
        for (int j = 0; j < 4; j++) {
            float2 v = unpack2(acc[i][j]);
            int n = n0 + tn0 + j * 2;
            int t = n >> 5, b = n & 31;
            long off = ((long)dir * TT + t) * (G4 * BB) + (long)g * BB + b;
            g_zpre[off]     = v.x + bias;
            g_zpre[off + 1] = v.y + bias;
        }
    }
}

// ============================================================================
// K1b: initialize h slots (pair-packed) and zero barriers
// ============================================================================
__global__ void k_inith(const float* __restrict__ h0)
{
    int dir = blockIdx.x;
    int tid = threadIdx.x;   // 256
    int slot = (dir == 0) ? 0 : TT;
    for (int s = tid; s < HHD * BB; s += 256) {
        int k = s >> 5, b = s & 31;
        int idx = slot * (HHD * BB) + (k >> 1) * 64 + b * 2 + (k & 1);
        g_hs[dir][idx] = h0[dir * (BB * HHD) + b * HHD + k];
    }
    if (blockIdx.x == 0) {
        for (int i = tid; i < 2 * TT; i += 256) g_bar[i] = 0;
    }
}

// ============================================================================
// K2: persistent bi-directional LSTM recurrence.
// 128 CTAs: dir = cid>>6, j-group = cid&63 (4 hidden units, 16 gate rows).
// Warp (w): kc = w>>1 (k-chunk of 64), rh = w&1 (8 gate rows).
// W slice resident in SMEM; read as LDS.128 (1 LDS : 2 fma2).
// ALL threads poll the step counter (no tid0-spin + syncthreads wakeup).
// ============================================================================
__global__ void __launch_bounds__(256, 1) k_lstm(
    const float* __restrict__ Whf, const float* __restrict__ Whb,
    const float* __restrict__ c0)
{
    __shared__ __align__(16) float Wsm[16][256];   // 16 KB
    __shared__ float zred[4][16][32];              // 8 KB
    __shared__ float csm[4][32];

    const int tid = threadIdx.x;
    const int w = tid >> 5, l = tid & 31;
    const int kc = w >> 1;          // 0..3 : k-chunk of 64
    const int rh = w & 1;           // 0..1 : row half (8 rows)
    const int cid = blockIdx.x;
    const int dir = cid >> 6;
    const int j0 = (cid & 63) * 4;
    const int jj = (tid >> 5) & 3;  // gate-phase warp index (tid<128)
    const int b  = l;

    const float* Wh = dir ? Whb : Whf;
#pragma unroll
    for (int i = 0; i < 4; i++) {
        int s = tid + i * 256;          // 0..1023 float4 slots
        int r = s >> 6;                 // 0..15
        int kq = (s & 63) << 2;
        int gate = r >> 2, jr = r & 3;
        float4 v = *(const float4*)(Wh + (gate * HHD + j0 + jr) * HHD + kq);
        *(float4*)&Wsm[r][kq] = v;
    }
    if (tid < 128) {
        csm[jj][b] = c0[dir * (BB * HHD) + b * HHD + j0 + jj];
    }
    __syncthreads();

    float* hsBase = g_hs[dir];
    int* bar = g_bar + dir * TT;
    const int zdirbase = dir * (TT * G4 * BB);

    for (int s = 0; s < TT; s++) {
        const int t = (dir == 0) ? s : (TT - 1 - s);
        const int rslot = (dir == 0) ? s : (t + 1);
        const int wslot = (dir == 0) ? (s + 1) : t;

        // ---- prefetch z_pre for this step (independent of barrier) ----
        float zp0, zp1, zp2, zp3;
        if (tid < 128) {
            const float* zb = g_zpre + zdirbase + t * (G4 * BB) + (j0 + jj) * BB + b;
            zp0 = zb[0 * HHD * BB];
            zp1 = zb[1 * HHD * BB];
            zp2 = zb[2 * HHD * BB];
            zp3 = zb[3 * HHD * BB];
        }

        // ---- wait for previous step's h (every thread polls) ----
        if (s > 0) {
            while (ldacq(&bar[s - 1]) < 64) { }
        }

        // ---- load this warp's 64-k chunk of h (32 x LDG.64, pair-packed) ----
        const ull* hp2 = (const ull*)(hsBase + rslot * (HHD * BB)) + kc * 32 * 32 + l;
        ull hreg2[32];
#pragma unroll
        for (int q = 0; q < 32; q++) hreg2[q] = hp2[q * 32];

        // ---- 8 rows x 64 k partial dots; W via LDS.128 ----
#pragma unroll
        for (int rr = 0; rr < 8; rr++) {
            const int r = rh * 8 + rr;
            const ulonglong2* W4 = (const ulonglong2*)&Wsm[r][kc * 64];
            ull a0 = 0ULL, a1 = 0ULL, a2 = 0ULL, a3 = 0ULL;
#pragma unroll
            for (int q4 = 0; q4 < 16; q4 += 2) {
                ulonglong2 wv0 = W4[q4];
                fma2(a0, wv0.x, hreg2[2 * q4]);
                fma2(a1, wv0.y, hreg2[2 * q4 + 1]);
                ulonglong2 wv1 = W4[q4 + 1];
                fma2(a2, wv1.x, hreg2[2 * q4 + 2]);
                fma2(a3, wv1.y, hreg2[2 * q4 + 3]);
            }
            float2 f0 = unpack2(a0), f1 = unpack2(a1);
            float2 f2 = unpack2(a2), f3 = unpack2(a3);
            zred[kc][r][l] = ((f0.x + f0.y) + (f1.x + f1.y))
                           + ((f2.x + f2.y) + (f3.x + f3.y));
        }
        __syncthreads();

        // ---- fused reduce(4 partials) + gates + h write (threads 0..127) ----
        if (tid < 128) {
            float zi = zp0, zf = zp1, zg = zp2, zo = zp3;
#pragma unroll
            for (int c = 0; c < 4; c++) {
                zi += zred[c][0 * 4 + jj][b];
                zf += zred[c][1 * 4 + jj][b];
                zg += zred[c][2 * 4 + jj][b];
                zo += zred[c][3 * 4 + jj][b];
            }
            float cc = sigf(zf) * csm[jj][b] + sigf(zi) * tanhf(zg);
            csm[jj][b] = cc;
            float h = sigf(zo) * tanhf(cc);
            int j = j0 + jj;
            hsBase[wslot * (HHD * BB) + (j >> 1) * 64 + b * 2 + (j & 1)] = h;
        }
        __syncthreads();
        if (tid == 0) redrel(&bar[s]);   // release orders the STG h above
    }
}

// ============================================================================
// K3: output projection. warp = tag (12 warps), lane = b.
// Pair-packed h gives natural (k,k+1) ull pairs -> pure fma2 loop.
// W read as broadcast LDG.64 (L1-cached across warps).
// ============================================================================
__global__ void __launch_bounds__(384) k_proj(
    const float* __restrict__ Wout, const float* __restrict__ bout)
{
    const int t = blockIdx.x;
    const int tid = threadIdx.x;
    const int tag = tid >> 5;         // 0..11
    const int l = tid & 31;           // batch

    const ull* w2f = (const ull*)(Wout + tag * 512);        // 128 pairs (fwd)
    const ull* w2b = w2f + 128;                             // 128 pairs (bwd)
    const ull* hf2 = (const ull*)(g_hs[0] + (t + 1) * (HHD * BB));
    const ull* hb2 = (const ull*)(g_hs[1] + t * (HHD * BB));

    ull a0 = 0ULL, a1 = 0ULL, a2 = 0ULL, a3 = 0ULL;
#pragma unroll
    for (int p = 0; p < 128; p += 4) {
        fma2(a0, w2f[p],     hf2[(p + 0) * 32 + l]);
        fma2(a1, w2f[p + 1], hf2[(p + 1) * 32 + l]);
        fma2(a2, w2f[p + 2], hf2[(p + 2) * 32 + l]);
        fma2(a3, w2f[p + 3], hf2[(p + 3) * 32 + l]);
    }
#pragma unroll
    for (int p = 0; p < 128; p += 4) {
        fma2(a0, w2b[p],     hb2[(p + 0) * 32 + l]);
        fma2(a1, w2b[p + 1], hb2[(p + 1) * 32 + l]);
        fma2(a2, w2b[p + 2], hb2[(p + 2) * 32 + l]);
        fma2(a3, w2b[p + 3], hb2[(p + 3) * 32 + l]);
    }
    float2 f0 = unpack2(a0), f1 = unpack2(a1);
    float2 f2 = unpack2(a2), f3 = unpack2(a3);
    float acc = ((f0.x + f0.y) + (f1.x + f1.y))
              + ((f2.x + f2.y) + (f3.x + f3.y)) + bout[tag];
    g_feats[(l * TT + t) * NT + tag] = acc;
}

// ============================================================================
// K4: Viterbi decode (one warp per batch element) + backtrace.
// feats preloaded into SMEM (removes LDG from the 256-step chain).
// out[0..31] = scores ; out[32 + b*T + t] = path tag (as float)
// ============================================================================
__global__ void __launch_bounds__(32) k_viterbi(
    const float* __restrict__ trans, float* __restrict__ out)
{
    __shared__ float tsm[NT * NT];
    __shared__ float fv[NT];
    __shared__ signed char bp[TT][NT];
    __shared__ float fsm[TT * NT];    // 12 KB

    const int b = blockIdx.x;
    const int tid = threadIdx.x;

    const float* fb = g_feats + (long)b * TT * NT;
    for (int i = tid; i < TT * NT; i += 32) fsm[i] = fb[i];
    for (int i = tid; i < NT * NT; i += 32) tsm[i] = trans[i];
    if (tid < NT) fv[tid] = (tid == START_IDX) ? 0.0f : -10000.0f;
    __syncwarp();

    for (int t = 0; t < TT; t++) {
        float bestv = -1e30f; int bestp = 0;
        if (tid < NT) {
            bestv = fv[0] + tsm[tid * NT + 0]; bestp = 0;
#pragma unroll
            for (int p = 1; p < NT; p++) {
                float v = fv[p] + tsm[tid * NT + p];
                if (v > bestv) { bestv = v; bestp = p; }
            }
        }
        __syncwarp();
        if (tid < NT) {
            fv[tid] = bestv + fsm[t * NT + tid];
            bp[t][tid] = (signed char)bestp;
        }
        __syncwarp();
    }

    if (tid == 0) {
        float best = fv[0] + tsm[STOP_IDX * NT + 0]; int bt = 0;
#pragma unroll
        for (int n = 1; n < NT; n++) {
            float v = fv[n] + tsm[STOP_IDX * NT + n];
            if (v > best) { best = v; bt = n; }
        }
        out[b] = best;
        int tag = bt;
        for (int t = TT - 1; t >= 0; t--) {
            out[32 + b * TT + t] = (float)tag;
            tag = bp[t][tag];
        }
    }
}

// ============================================================================
extern "C" void kernel_launch(void* const* d_in, const int* in_sizes, int n_in,
                              void* d_out, int out_size)
{
    const int*   sent  = (const int*)  d_in[0];
    const float* embed = (const float*)d_in[1];
    const float* Wihf  = (const float*)d_in[2];
    const float* Whhf  = (const float*)d_in[3];
    const float* bf    = (const float*)d_in[4];
    const float* Wihb  = (const float*)d_in[5];
    const float* Whhb  = (const float*)d_in[6];
    const float* bb    = (const float*)d_in[7];
    const float* Wout  = (const float*)d_in[8];
    const float* bout  = (const float*)d_in[9];
    const float* trans = (const float*)d_in[10];
    const float* h0    = (const float*)d_in[11];
    const float* c0    = (const float*)d_in[12];
    float* out = (float*)d_out;

    k_ingemm<<<dim3(64, 16), 256>>>(sent, embed, Wihf, Wihb, bf, bb);
    k_inith<<<2, 256>>>(h0);
    k_lstm<<<128, 256>>>(Whhf, Whhb, c0);
    k_proj<<<TT, 384>>>(Wout, bout);
    k_viterbi<<<BB, 32>>>(trans, out);
}

// round 7
// speedup vs baseline: 1.4272x; 1.1655x over previous
#include <cuda_runtime.h>
#include <cuda_bf16.h>
#include <cstdint>

// Problem constants
#define TT   256     // sequence length
#define BB   32      // batch
#define EMB  256
#define HHD  256     // per-direction hidden
#define G4   1024    // 4*HHD
#define NT   12
#define START_IDX 10
#define STOP_IDX  11

typedef unsigned long long ull;

// ---------------- scratch (device globals; no allocation allowed) ----------
__device__ __align__(16) float g_zpre[2L * TT * G4 * BB];   // [dir][t][gate_row][b]
// h stored PAIR-PACKED: linear idx = slot*8192 + (k>>1)*64 + b*2 + (k&1)
__device__ __align__(16) float g_hs[2][(TT + 1) * HHD * BB];
__device__ __align__(16) float g_feats[BB * TT * NT];       // [b][t][tag]
__device__ int   g_bar[2 * TT];                             // per-dir per-step counters
// bf16 split operands for the tensor-core input GEMM
__device__ __align__(16) __nv_bfloat16 g_Whi[2048 * 256];   // rows m = dir*1024 + (gate*256+j)
__device__ __align__(16) __nv_bfloat16 g_Wlo[2048 * 256];
__device__ __align__(16) __nv_bfloat16 g_xhi[8192 * 256];   // rows n = t*32 + b
__device__ __align__(16) __nv_bfloat16 g_xlo[8192 * 256];

// ---------------- generic helpers ------------------------------------------
__device__ __forceinline__ void fma2(ull& d, ull a, ull b) {
    asm volatile("fma.rn.f32x2 %0, %1, %2, %0;" : "+l"(d) : "l"(a), "l"(b));
}
__device__ __forceinline__ ull pack2(float x, float y) {
    ull r; asm("mov.b64 %0, {%1, %2};" : "=l"(r) : "f"(x), "f"(y)); return r;
}
__device__ __forceinline__ float2 unpack2(ull v) {
    float2 f; asm("mov.b64 {%0, %1}, %2;" : "=f"(f.x), "=f"(f.y) : "l"(v)); return f;
}
__device__ __forceinline__ int ldacq(const int* p) {
    int v; asm volatile("ld.acquire.gpu.global.s32 %0, [%1];" : "=r"(v) : "l"(p)); return v;
}
__device__ __forceinline__ void redrel(int* p) {
    asm volatile("red.release.gpu.global.add.s32 [%0], 1;" :: "l"(p));
}
__device__ __forceinline__ float sigf(float x) { return 1.0f / (1.0f + __expf(-x)); }
__device__ __forceinline__ uint32_t smem_u32(const void* p) {
    uint32_t a;
    asm("{ .reg .u64 t; cvta.to.shared.u64 t, %1; cvt.u32.u64 %0, t; }" : "=r"(a) : "l"(p));
    return a;
}
__device__ __forceinline__ void ldsm4(uint32_t& r0, uint32_t& r1, uint32_t& r2, uint32_t& r3,
                                      uint32_t addr) {
    asm volatile("ldmatrix.sync.aligned.m8n8.x4.shared.b16 {%0,%1,%2,%3}, [%4];"
                 : "=r"(r0), "=r"(r1), "=r"(r2), "=r"(r3) : "r"(addr));
}
__device__ __forceinline__ void mma16816(float* c, const uint32_t* a, const uint32_t* b) {
    asm volatile("mma.sync.aligned.m16n8k16.row.col.f32.bf16.bf16.f32 "
                 "{%0,%1,%2,%3}, {%4,%5,%6,%7}, {%8,%9}, {%0,%1,%2,%3};"
                 : "+f"(c[0]), "+f"(c[1]), "+f"(c[2]), "+f"(c[3])
                 : "r"(a[0]), "r"(a[1]), "r"(a[2]), "r"(a[3]), "r"(b[0]), "r"(b[1]));
}

// ============================================================================
// K0a: convert W_ih (both dirs) to bf16 hi/lo.  m = dir*1024 + row
// ============================================================================
__global__ void k_convW(const float* __restrict__ Wf, const float* __restrict__ Wb)
{
    int m = blockIdx.x;          // 0..2047
    int k = threadIdx.x;         // 0..255
    const float* W = (m < 1024) ? Wf : Wb;
    float v = W[(m & 1023) * 256 + k];
    __nv_bfloat16 hi = __float2bfloat16(v);
    float r = v - __bfloat162float(hi);
    g_Whi[m * 256 + k] = hi;
    g_Wlo[m * 256 + k] = __float2bfloat16(r);
}

// ============================================================================
// K0b: gather embeddings and convert to bf16 hi/lo.  n = t*32 + b
// ============================================================================
__global__ void k_convX(const int* __restrict__ sent, const float* __restrict__ embed)
{
    int n = blockIdx.x;          // 0..8191
    int t = n >> 5, b = n & 31;
    int word = sent[b * TT + t];
    int k = threadIdx.x;         // 0..255
    float v = embed[(long)word * 256 + k];
    __nv_bfloat16 hi = __float2bfloat16(v);
    float r = v - __bfloat162float(hi);
    g_xhi[n * 256 + k] = hi;
    g_xlo[n * 256 + k] = __float2bfloat16(r);
}

// ============================================================================
// K1: tensor-core input GEMM via mma.sync bf16 split (Wh*xh + Wh*xl + Wl*xh).
// CTA tile 128x128, 8 warps (2x4), warp tile 64x32, K chunks of 32.
// SMEM rows padded to stride 40 bf16 (80B) -> conflict-free ldmatrix.
// grid = (8192/128, 2048/128) = (64, 16).
// ============================================================================
#define ASTR 40
__global__ void __launch_bounds__(256, 2) k_ingemm_mma(
    const float* __restrict__ bf, const float* __restrict__ bb)
{
    __shared__ __align__(16) __nv_bfloat16 sAh[128 * ASTR];
    __shared__ __align__(16) __nv_bfloat16 sAl[128 * ASTR];
    __shared__ __align__(16) __nv_bfloat16 sBh[128 * ASTR];
    __shared__ __align__(16) __nv_bfloat16 sBl[128 * ASTR];

    const int tid = threadIdx.x;
    const int wid = tid >> 5, lane = tid & 31;
    const int m0 = blockIdx.y * 128;
    const int n0 = blockIdx.x * 128;
    const int wm = (wid >> 2) * 64;     // warp m base within tile
    const int wn = (wid & 3) * 32;      // warp n base within tile

    float acc[4][4][4];
#pragma unroll
    for (int i = 0; i < 4; i++)
#pragma unroll
        for (int j = 0; j < 4; j++)
#pragma unroll
            for (int q = 0; q < 4; q++) acc[i][j][q] = 0.f;

    const uint32_t aAh = smem_u32(sAh), aAl = smem_u32(sAl);
    const uint32_t aBh = smem_u32(sBh), aBl = smem_u32(sBl);

    const int arow = lane & 15;                 // A frag row within 16
    const int akq  = (lane >> 4) * 16;          // A frag col bytes (0/16)
    const int brow = (lane & 7) + ((lane >> 4) << 3);   // B frag row within 16
    const int bkq  = ((lane >> 3) & 1) * 16;            // B frag col bytes

    for (int kc = 0; kc < 8; kc++) {
        __syncthreads();
        for (int i = tid; i < 512; i += 256) {
            int r = i >> 2, cq = (i & 3) << 3;      // 8-bf16 quads
            long srcA = (long)(m0 + r) * 256 + kc * 32 + cq;
            *(int4*)(sAh + r * ASTR + cq) = *(const int4*)(g_Whi + srcA);
            *(int4*)(sAl + r * ASTR + cq) = *(const int4*)(g_Wlo + srcA);
            long srcB = (long)(n0 + r) * 256 + kc * 32 + cq;
            *(int4*)(sBh + r * ASTR + cq) = *(const int4*)(g_xhi + srcB);
            *(int4*)(sBl + r * ASTR + cq) = *(const int4*)(g_xlo + srcB);
        }
        __syncthreads();

#pragma unroll
        for (int ks = 0; ks < 2; ks++) {
            const int akb = ks * 32 + akq;     // bytes within 64B k-chunk
            const int bkb = ks * 32 + bkq;

            uint32_t Ah[4][4], Bh[4][2], Bl[4][2];
#pragma unroll
            for (int mf = 0; mf < 4; mf++) {
                uint32_t ad = aAh + (uint32_t)((wm + mf * 16 + arow) * (ASTR * 2)) + akb;
                ldsm4(Ah[mf][0], Ah[mf][1], Ah[mf][2], Ah[mf][3], ad);
            }
#pragma unroll
            for (int nf2 = 0; nf2 < 2; nf2++) {
                uint32_t bo = (uint32_t)((wn + nf2 * 16 + brow) * (ASTR * 2)) + bkb;
                uint32_t r0, r1, r2, r3;
                ldsm4(r0, r1, r2, r3, aBh + bo);
                Bh[nf2 * 2][0] = r0; Bh[nf2 * 2][1] = r1;
                Bh[nf2 * 2 + 1][0] = r2; Bh[nf2 * 2 + 1][1] = r3;
                ldsm4(r0, r1, r2, r3, aBl + bo);
                Bl[nf2 * 2][0] = r0; Bl[nf2 * 2][1] = r1;
                Bl[nf2 * 2 + 1][0] = r2; Bl[nf2 * 2 + 1][1] = r3;
            }
            // hi*hi and hi*lo passes
#pragma unroll
            for (int mf = 0; mf < 4; mf++)
#pragma unroll
                for (int nf = 0; nf < 4; nf++) {
                    mma16816(acc[mf][nf], Ah[mf], Bh[nf]);
                    mma16816(acc[mf][nf], Ah[mf], Bl[nf]);
                }
            // lo*hi pass (reload A as lo)
#pragma unroll
            for (int mf = 0; mf < 4; mf++) {
                uint32_t Al[4];
                uint32_t ad = aAl + (uint32_t)((wm + mf * 16 + arow) * (ASTR * 2)) + akb;
                ldsm4(Al[0], Al[1], Al[2], Al[3], ad);
#pragma unroll
                for (int nf = 0; nf < 4; nf++)
                    mma16816(acc[mf][nf], Al, Bh[nf]);
            }
        }
    }

    // ---- epilogue: c{0,1} at (m, n..n+1), c{2,3} at (m+8, n..n+1) ----
#pragma unroll
    for (int mf = 0; mf < 4; mf++) {
        int m = m0 + wm + mf * 16 + (lane >> 2);
        int dirA = m >> 10, gA = m & 1023;
        int mB = m + 8;
        int gB = mB & 1023;
        float biasA = dirA ? bb[gA] : bf[gA];
        float biasB = (mB >> 10) ? bb[gB] : bf[gB];
#pragma unroll
        for (int nf = 0; nf < 4; nf++) {
            int n = n0 + wn + nf * 8 + 2 * (lane & 3);
            int t = n >> 5, b = n & 31;
            float* zpA = g_zpre + ((long)dirA * TT + t) * (G4 * BB) + (long)gA * BB + b;
            float2 vA = make_float2(acc[mf][nf][0] + biasA, acc[mf][nf][1] + biasA);
            *(float2*)zpA = vA;
            float* zpB = g_zpre + ((long)(mB >> 10) * TT + t) * (G4 * BB) + (long)gB * BB + b;
            float2 vB = make_float2(acc[mf][nf][2] + biasB, acc[mf][nf][3] + biasB);
            *(float2*)zpB = vB;
        }
    }
}

// ============================================================================
// K1b: initialize h slots (pair-packed) and zero barriers
// ============================================================================
__global__ void k_inith(const float* __restrict__ h0)
{
    int dir = blockIdx.x;
    int tid = threadIdx.x;   // 256
    int slot = (dir == 0) ? 0 : TT;
    for (int s = tid; s < HHD * BB; s += 256) {
        int k = s >> 5, b = s & 31;
        int idx = slot * (HHD * BB) + (k >> 1) * 64 + b * 2 + (k & 1);
        g_hs[dir][idx] = h0[dir * (BB * HHD) + b * HHD + k];
    }
    if (blockIdx.x == 0) {
        for (int i = tid; i < 2 * TT; i += 256) g_bar[i] = 0;
    }
}

// ============================================================================
// K2: persistent bi-directional LSTM recurrence.
// 128 CTAs: dir = cid>>6, j-group = cid&63 (4 hidden units, 16 gate rows).
// tid0-only acquire poll + syncthreads (avoids LTS poll storm).
// ============================================================================
__global__ void __launch_bounds__(256, 1) k_lstm(
    const float* __restrict__ Whf, const float* __restrict__ Whb,
    const float* __restrict__ c0)
{
    __shared__ __align__(16) float Wsm[16][256];   // 16 KB
    __shared__ float zred[4][16][32];              // 8 KB
    __shared__ float csm[4][32];

    const int tid = threadIdx.x;
    const int w = tid >> 5, l = tid & 31;
    const int kc = w >> 1;          // 0..3 : k-chunk of 64
    const int rh = w & 1;           // 0..1 : row half (8 rows)
    const int cid = blockIdx.x;
    const int dir = cid >> 6;
    const int j0 = (cid & 63) * 4;
    const int jj = (tid >> 5) & 3;  // gate-phase warp index (tid<128)
    const int b  = l;

    const float* Wh = dir ? Whb : Whf;
#pragma unroll
    for (int i = 0; i < 4; i++) {
        int s = tid + i * 256;          // 0..1023 float4 slots
        int r = s >> 6;                 // 0..15
        int kq = (s & 63) << 2;
        int gate = r >> 2, jr = r & 3;
        float4 v = *(const float4*)(Wh + (gate * HHD + j0 + jr) * HHD + kq);
        *(float4*)&Wsm[r][kq] = v;
    }
    if (tid < 128) {
        csm[jj][b] = c0[dir * (BB * HHD) + b * HHD + j0 + jj];
    }
    __syncthreads();

    float* hsBase = g_hs[dir];
    int* bar = g_bar + dir * TT;
    const long zdirbase = (long)dir * (TT * G4 * BB);

    for (int s = 0; s < TT; s++) {
        const int t = (dir == 0) ? s : (TT - 1 - s);
        const int rslot = (dir == 0) ? s : (t + 1);
        const int wslot = (dir == 0) ? (s + 1) : t;

        // ---- prefetch z_pre for this step (independent of barrier) ----
        float zp0, zp1, zp2, zp3;
        if (tid < 128) {
            const float* zb = g_zpre + zdirbase + (long)t * (G4 * BB) + (j0 + jj) * BB + b;
            zp0 = zb[0 * HHD * BB];
            zp1 = zb[1 * HHD * BB];
            zp2 = zb[2 * HHD * BB];
            zp3 = zb[3 * HHD * BB];
        }

        // ---- wait for previous step's h (tid0 poll, then block sync) ----
        if (s > 0) {
            if (tid == 0) {
                while (ldacq(&bar[s - 1]) < 64) { }
            }
            __syncthreads();
        }

        // ---- load this warp's 64-k chunk of h (pair-packed LDG.64) ----
        const ull* hp2 = (const ull*)(hsBase + rslot * (HHD * BB)) + kc * 32 * 32 + l;
        ull hreg2[32];
#pragma unroll
        for (int q = 0; q < 32; q++) hreg2[q] = hp2[q * 32];

        // ---- 8 rows x 64 k partial dots; W via LDS.128 ----
#pragma unroll
        for (int rr = 0; rr < 8; rr++) {
            const int r = rh * 8 + rr;
            const ulonglong2* W4 = (const ulonglong2*)&Wsm[r][kc * 64];
            ull a0 = 0ULL, a1 = 0ULL, a2 = 0ULL, a3 = 0ULL;
#pragma unroll
            for (int q4 = 0; q4 < 16; q4 += 2) {
                ulonglong2 wv0 = W4[q4];
                fma2(a0, wv0.x, hreg2[2 * q4]);
                fma2(a1, wv0.y, hreg2[2 * q4 + 1]);
                ulonglong2 wv1 = W4[q4 + 1];
                fma2(a2, wv1.x, hreg2[2 * q4 + 2]);
                fma2(a3, wv1.y, hreg2[2 * q4 + 3]);
            }
            float2 f0 = unpack2(a0), f1 = unpack2(a1);
            float2 f2 = unpack2(a2), f3 = unpack2(a3);
            zred[kc][r][l] = ((f0.x + f0.y) + (f1.x + f1.y))
                           + ((f2.x + f2.y) + (f3.x + f3.y));
        }
        __syncthreads();

        // ---- fused reduce(4 partials) + gates + h write (threads 0..127) ----
        if (tid < 128) {
            float zi = zp0, zf = zp1, zg = zp2, zo = zp3;
#pragma unroll
            for (int c = 0; c < 4; c++) {
                zi += zred[c][0 * 4 + jj][b];
                zf += zred[c][1 * 4 + jj][b];
                zg += zred[c][2 * 4 + jj][b];
                zo += zred[c][3 * 4 + jj][b];
            }
            float cc = sigf(zf) * csm[jj][b] + sigf(zi) * tanhf(zg);
            csm[jj][b] = cc;
            float h = sigf(zo) * tanhf(cc);
            int j = j0 + jj;
            hsBase[wslot * (HHD * BB) + (j >> 1) * 64 + b * 2 + (j & 1)] = h;
        }
        __syncthreads();
        if (tid == 0) redrel(&bar[s]);   // release orders the STG h above
    }
}

// ============================================================================
// K3: output projection.  SMEM-staged h (64KB) + fma2. warp=tag, lane=b.
// ============================================================================
__global__ void __launch_bounds__(384) k_proj(
    const float* __restrict__ Wout, const float* __restrict__ bout)
{
    extern __shared__ float hsm[];    // [2][8192] floats = 64 KB
    const int t = blockIdx.x;
    const int tid = threadIdx.x;
    const int tag = tid >> 5;         // 0..11
    const int l = tid & 31;           // batch

    const float4* hf = (const float4*)(g_hs[0] + (t + 1) * (HHD * BB));
    const float4* hb = (const float4*)(g_hs[1] + t * (HHD * BB));
    float4* sf = (float4*)hsm;
    float4* sbp = (float4*)(hsm + HHD * BB);
    for (int i = tid; i < (HHD * BB) / 4; i += 384) {
        sf[i] = hf[i];
        sbp[i] = hb[i];
    }
    __syncthreads();

    const ull* w2f = (const ull*)(Wout + tag * 512);
    const ull* w2b = w2f + 128;
    const ull* hf2 = (const ull*)hsm;
    const ull* hb2 = (const ull*)(hsm + HHD * BB);

    ull a0 = 0ULL, a1 = 0ULL, a2 = 0ULL, a3 = 0ULL;
#pragma unroll
    for (int p = 0; p < 128; p += 4) {
        fma2(a0, w2f[p],     hf2[(p + 0) * 32 + l]);
        fma2(a1, w2f[p + 1], hf2[(p + 1) * 32 + l]);
        fma2(a2, w2f[p + 2], hf2[(p + 2) * 32 + l]);
        fma2(a3, w2f[p + 3], hf2[(p + 3) * 32 + l]);
    }
#pragma unroll
    for (int p = 0; p < 128; p += 4) {
        fma2(a0, w2b[p],     hb2[(p + 0) * 32 + l]);
        fma2(a1, w2b[p + 1], hb2[(p + 1) * 32 + l]);
        fma2(a2, w2b[p + 2], hb2[(p + 2) * 32 + l]);
        fma2(a3, w2b[p + 3], hb2[(p + 3) * 32 + l]);
    }
    float2 f0 = unpack2(a0), f1 = unpack2(a1);
    float2 f2 = unpack2(a2), f3 = unpack2(a3);
    float acc = ((f0.x + f0.y) + (f1.x + f1.y))
              + ((f2.x + f2.y) + (f3.x + f3.y)) + bout[tag];
    g_feats[(l * TT + t) * NT + tag] = acc;
}

// ============================================================================
// K4: Viterbi decode (one warp per batch element) + backtrace.
// ============================================================================
__global__ void __launch_bounds__(32) k_viterbi(
    const float* __restrict__ trans, float* __restrict__ out)
{
    __shared__ float tsm[NT * NT];
    __shared__ float fv[NT];
    __shared__ signed char bp[TT][NT];
    __shared__ float fsm[TT * NT];    // 12 KB

    const int b = blockIdx.x;
    const int tid = threadIdx.x;

    const float* fb = g_feats + (long)b * TT * NT;
    for (int i = tid; i < TT * NT; i += 32) fsm[i] = fb[i];
    for (int i = tid; i < NT * NT; i += 32) tsm[i] = trans[i];
    if (tid < NT) fv[tid] = (tid == START_IDX) ? 0.0f : -10000.0f;
    __syncwarp();

    for (int t = 0; t < TT; t++) {
        float bestv = -1e30f; int bestp = 0;
        if (tid < NT) {
            bestv = fv[0] + tsm[tid * NT + 0]; bestp = 0;
#pragma unroll
            for (int p = 1; p < NT; p++) {
                float v = fv[p] + tsm[tid * NT + p];
                if (v > bestv) { bestv = v; bestp = p; }
            }
        }
        __syncwarp();
        if (tid < NT) {
            fv[tid] = bestv + fsm[t * NT + tid];
            bp[t][tid] = (signed char)bestp;
        }
        __syncwarp();
    }

    if (tid == 0) {
        float best = fv[0] + tsm[STOP_IDX * NT + 0]; int bt = 0;
#pragma unroll
        for (int n = 1; n < NT; n++) {
            float v = fv[n] + tsm[STOP_IDX * NT + n];
            if (v > best) { best = v; bt = n; }
        }
        out[b] = best;
        int tag = bt;
        for (int t = TT - 1; t >= 0; t--) {
            out[32 + b * TT + t] = (float)tag;
            tag = bp[t][tag];
        }
    }
}

// ============================================================================
extern "C" void kernel_launch(void* const* d_in, const int* in_sizes, int n_in,
                              void* d_out, int out_size)
{
    const int*   sent  = (const int*)  d_in[0];
    const float* embed = (const float*)d_in[1];
    const float* Wihf  = (const float*)d_in[2];
    const float* Whhf  = (const float*)d_in[3];
    const float* bf    = (const float*)d_in[4];
    const float* Wihb  = (const float*)d_in[5];
    const float* Whhb  = (const float*)d_in[6];
    const float* bb    = (const float*)d_in[7];
    const float* Wout  = (const float*)d_in[8];
    const float* bout  = (const float*)d_in[9];
    const float* trans = (const float*)d_in[10];
    const float* h0    = (const float*)d_in[11];
    const float* c0    = (const float*)d_in[12];
    float* out = (float*)d_out;

    cudaFuncSetAttribute(k_proj, cudaFuncAttributeMaxDynamicSharedMemorySize, 65536);

    k_convW<<<2048, 256>>>(Wihf, Wihb);
    k_convX<<<8192, 256>>>(sent, embed);
    k_inith<<<2, 256>>>(h0);
    k_ingemm_mma<<<dim3(64, 16), 256>>>(bf, bb);
    k_lstm<<<128, 256>>>(Whhf, Whhb, c0);
    k_proj<<<TT, 384, 65536>>>(Wout, bout);
    k_viterbi<<<BB, 32>>>(trans, out);
}